// round 2
// baseline (speedup 1.0000x reference)
#include <cuda_runtime.h>
#include <math.h>

#define BATCH 16
#define CH    64
#define NPIX  65536
#define NBVEC 4
#define TILE  128            // pixels per k_main block
#define NBLK  (NPIX / TILE)  // 512 x-blocks

// Scratch (device globals; no runtime allocation allowed)
__device__ float g_score[BATCH * NPIX];
__device__ unsigned long long g_best[NBVEC * BATCH];   // packed (score_bits<<32)|(~index)
__device__ float g_repr[NBVEC * BATCH * CH];
__device__ float g_sumsim[NBVEC * BATCH];

// ---------------------------------------------------------------------------
// Init: copy score, zero selectedPos output, zero accumulators & argmax cells
// ---------------------------------------------------------------------------
__global__ void k_init(const float* __restrict__ score_init, float* __restrict__ pos_out) {
    int i = blockIdx.x * blockDim.x + threadIdx.x;
    int total = BATCH * NPIX;
    for (int k = i; k < total; k += gridDim.x * blockDim.x) {
        g_score[k] = score_init[k];
        pos_out[k] = 0.0f;
    }
    if (i < NBVEC * BATCH * CH) g_repr[i] = 0.0f;
    if (i < NBVEC * BATCH) { g_sumsim[i] = 0.0f; g_best[i] = 0ull; }
}

// ---------------------------------------------------------------------------
// Distributed argmax: grid (32 segs, BATCH). score >= 0 always, so float bits
// are order-preserving as uint. Low 32 bits = ~index -> first-index tie-break.
// ---------------------------------------------------------------------------
__global__ __launch_bounds__(256) void k_argmax(int it) {
    __shared__ unsigned long long ws[8];
    int b   = blockIdx.y;
    int tid = threadIdx.x;
    int base = blockIdx.x * (NPIX / 32);   // 2048 pixels per block

    const float* sc = g_score + (size_t)b * NPIX + base;
    unsigned long long best = 0ull;
#pragma unroll
    for (int k = 0; k < 8; k++) {
        int n = k * 256 + tid;
        unsigned long long p = ((unsigned long long)__float_as_uint(sc[n]) << 32)
                             | (unsigned long long)(0xFFFFFFFFu - (unsigned)(base + n));
        best = max(best, p);
    }
#pragma unroll
    for (int o = 16; o > 0; o >>= 1)
        best = max(best, __shfl_down_sync(0xffffffffu, best, o));
    if ((tid & 31) == 0) ws[tid >> 5] = best;
    __syncthreads();
    if (tid < 32) {
        best = (tid < 8) ? ws[tid] : 0ull;
#pragma unroll
        for (int o = 4; o > 0; o >>= 1)
            best = max(best, __shfl_down_sync(0xffffffffu, best, o));
        if (tid == 0) atomicMax(&g_best[it * BATCH + b], best);
    }
}

// ---------------------------------------------------------------------------
// Main pass, register-resident. Block = 128 pixels, 256 threads.
// Thread: r = tid>>5 (warp id), j = (tid&31)*4. Owns channels 8r..8r+7 of
// pixels base+j..base+j+3, kept in 8 float4 registers.
// ---------------------------------------------------------------------------
__global__ __launch_bounds__(256, 4) void k_main(const float* __restrict__ x,
                                                 float* __restrict__ sim_out,
                                                 int it) {
    __shared__ float pd2S[8 * TILE];   // per-warp-row d2 partials
    __shared__ float simS[TILE];
    __shared__ float rawS[CH];

    int b    = blockIdx.y;
    int base = blockIdx.x * TILE;
    int tid  = threadIdx.x;
    int r    = tid >> 5;
    int lane = tid & 31;
    int j    = lane << 2;

    // decode selected index (uniform broadcast load)
    unsigned long long packed = g_best[it * BATCH + b];
    int ind = (int)(0xFFFFFFFFu - (unsigned)(packed & 0xFFFFFFFFull));

    const float* xb = x + (size_t)b * CH * NPIX;
    if (tid < CH) rawS[tid] = xb[(size_t)tid * NPIX + ind];

    // load 8 float4 into registers (channels 8r..8r+7, pixels base+j..+3)
    float4 v[8];
#pragma unroll
    for (int l = 0; l < 8; l++) {
        int c = r * 8 + l;
        v[l] = *(const float4*)(xb + (size_t)c * NPIX + base + j);
    }
    __syncthreads();   // rawS visible

    // d2 partials over this thread's 8 channels
    float p0 = 0.f, p1 = 0.f, p2 = 0.f, p3 = 0.f;
#pragma unroll
    for (int l = 0; l < 8; l++) {
        float rw = rawS[r * 8 + l];
        float d;
        d = v[l].x - rw; p0 = fmaf(d, d, p0);
        d = v[l].y - rw; p1 = fmaf(d, d, p1);
        d = v[l].z - rw; p2 = fmaf(d, d, p2);
        d = v[l].w - rw; p3 = fmaf(d, d, p3);
    }
    *(float4*)&pd2S[r * TILE + j] = make_float4(p0, p1, p2, p3);
    __syncthreads();

    // phase 1: combine partials, sim, outputs, score suppression, sum(sim)
    if (tid < TILE) {
        float d2 = 0.f;
#pragma unroll
        for (int q = 0; q < 8; q++) d2 += pd2S[q * TILE + tid];
        float sim = expf(-sqrtf(fmaxf(d2, 1e-12f)) * 0.05f);
        simS[tid] = sim;
        sim_out[((size_t)b * NBVEC + it) * NPIX + base + tid] = sim;
        float* sp = g_score + (size_t)b * NPIX + base + tid;
        *sp = (1.0f - sim) * (*sp);
        float s = sim;
#pragma unroll
        for (int o = 16; o > 0; o >>= 1) s += __shfl_down_sync(0xffffffffu, s, o);
        if (lane == 0) atomicAdd(&g_sumsim[it * BATCH + b], s);
    }
    __syncthreads();

    // phase 2: repr numerator from registers; warp r owns channels 8r..8r+7
    float4 sf = *(const float4*)&simS[j];
    float* gr = g_repr + ((size_t)it * BATCH + b) * CH + r * 8;
#pragma unroll
    for (int l = 0; l < 8; l++) {
        float pr = v[l].x * sf.x + v[l].y * sf.y + v[l].z * sf.z + v[l].w * sf.w;
#pragma unroll
        for (int o = 16; o > 0; o >>= 1) pr += __shfl_down_sync(0xffffffffu, pr, o);
        if (lane == 0) atomicAdd(gr + l, pr);
    }
}

// ---------------------------------------------------------------------------
// Finalize all iterations: vecList[b, it, c] = repr / sumSim
// ---------------------------------------------------------------------------
__global__ void k_fin(float* __restrict__ vec_out) {
    int b   = blockIdx.x;
    int it  = threadIdx.x >> 6;
    int c   = threadIdx.x & 63;
    vec_out[((size_t)b * NBVEC + it) * CH + c] =
        g_repr[((size_t)it * BATCH + b) * CH + c] / g_sumsim[it * BATCH + b];
}

// ---------------------------------------------------------------------------
extern "C" void kernel_launch(void* const* d_in, const int* in_sizes, int n_in,
                              void* d_out, int out_size) {
    const float* x          = (const float*)d_in[0];  // [16,64,256,256] fp32
    const float* score_init = (const float*)d_in[1];  // [16,65536] fp32
    float* out = (float*)d_out;

    float* vec_out = out;                                      // [16,4,64]
    float* sim_out = out + (size_t)BATCH * NBVEC * CH;         // [16,4,65536]
    float* pos_out = sim_out + (size_t)BATCH * NBVEC * NPIX;   // [16,1,65536]

    k_init<<<1024, 256>>>(score_init, pos_out);
    for (int it = 0; it < NBVEC; it++) {
        k_argmax<<<dim3(32, BATCH), 256>>>(it);
        k_main<<<dim3(NBLK, BATCH), 256>>>(x, sim_out, it);
    }
    k_fin<<<BATCH, NBVEC * CH>>>(vec_out);
}